// round 6
// baseline (speedup 1.0000x reference)
#include <cuda_runtime.h>
#include <cstdint>

#define BATCH 64
#define NSEQ  2048
#define CDIM  128
#define HP    64
#define WP    32
#define HG    32   // HP / POOL
#define D_SCALE 0.08838834764831845f  // 1/sqrt(128)

// Scratch: Q,K,V in [B, C, N] (spatial-major) layout. V plane is overwritten
// with the attention output by attn_kernel (each CTA exclusively owns its plane,
// and proj writes it fully on every graph replay -> deterministic).
__device__ float g_QT[(size_t)BATCH * CDIM * NSEQ];
__device__ float g_KT[(size_t)BATCH * CDIM * NSEQ];
__device__ float g_VT[(size_t)BATCH * CDIM * NSEQ];

#define SSTR 132   // proj smem row stride (floats)
#define KSTR 36    // attn smem row stride: (36*lane + w) % 32 = 4*lane + w -> LDS.128 conflict-free

// Pack two fp32 into bf16x2: e0 -> low 16 bits (even k), e1 -> high (odd k).
__device__ __forceinline__ uint32_t bf16x2_of(float e0, float e1) {
    uint32_t r;
    asm("cvt.rn.bf16x2.f32 %0, %1, %2;" : "=r"(r) : "f"(e1), "f"(e0));
    return r;
}
__device__ __forceinline__ float lo_f(uint32_t p) { return __uint_as_float(p << 16); }
__device__ __forceinline__ float hi_f(uint32_t p) { return __uint_as_float(p & 0xffff0000u); }

__device__ __forceinline__ void mma_bf16(float& d0, float& d1, float& d2, float& d3,
                                         uint32_t a0, uint32_t a1, uint32_t a2, uint32_t a3,
                                         uint32_t b0, uint32_t b1) {
    asm volatile(
        "mma.sync.aligned.m16n8k16.row.col.f32.bf16.bf16.f32 "
        "{%0,%1,%2,%3}, {%4,%5,%6,%7}, {%8,%9}, {%0,%1,%2,%3};"
        : "+f"(d0), "+f"(d1), "+f"(d2), "+f"(d3)
        : "r"(a0), "r"(a1), "r"(a2), "r"(a3), "r"(b0), "r"(b1));
}

// ---------------------------------------------------------------------------
// Kernel 1: projection GEMMs (R4 version — proven 239us).
// 3-term bf16 split (hi*hi + lo*hi + hi*lo). 512 threads = 16 warps.
// ---------------------------------------------------------------------------
__global__ __launch_bounds__(512) void proj_mma_kernel(
    const float* __restrict__ X,
    const float* __restrict__ Wq, const float* __restrict__ bq,
    const float* __restrict__ Wk, const float* __restrict__ bk,
    const float* __restrict__ Wv, const float* __restrict__ bv)
{
    extern __shared__ float sm[];
    float* Xs  = sm;                        // [m][c] 128 x SSTR fp32 (67.6 KB)
    uint4* Wpk = (uint4*)(sm + 128 * SSTR); // [16 nt][8 ks][32 lane] uint4 (64 KB)

    const int t    = threadIdx.x;
    const int warp = t >> 5;
    const int lane = t & 31;
    const int M0   = blockIdx.x * 128;
    const int bidx = M0 >> 11;
    const int n0   = M0 & 2047;

    {
        const int r  = t >> 5;
        const int c4 = (t & 31) << 2;
        #pragma unroll
        for (int it = 0; it < 8; ++it) {
            const int row = it * 16 + r;
            float4 xv = *(const float4*)(X + (size_t)(M0 + row) * CDIM + c4);
            *(float4*)(Xs + row * SSTR + c4) = xv;
        }
    }

    const int g      = lane >> 2;
    const int tid    = lane & 3;
    const int mgroup = warp & 7;
    const int nhalf  = warp >> 3;
    const int mbase  = mgroup * 16;

    #pragma unroll 1
    for (int p = 0; p < 3; ++p) {
        const float* W    = (p == 0) ? Wq : (p == 1) ? Wk : Wv;
        const float* bias = (p == 0) ? bq : (p == 1) ? bk : bv;
        float* OutT       = (p == 0) ? g_QT : (p == 1) ? g_KT : g_VT;

        __syncthreads();

        {
            const int r      = t >> 5;
            const int c4     = (t & 31) << 2;
            const int ks     = c4 >> 4;
            const int hiword = ((c4 & 15) >= 8) ? 1 : 0;
            const int tidA   = (c4 & 7) >> 1;
            #pragma unroll
            for (int it = 0; it < 8; ++it) {
                const int j  = it * 16 + r;
                const int nt = j >> 3;
                const int gj = j & 7;
                float4 wv = *(const float4*)(W + (size_t)j * CDIM + c4);
                uint32_t hiA = bf16x2_of(wv.x, wv.y);
                uint32_t hiB = bf16x2_of(wv.z, wv.w);
                uint32_t loA = bf16x2_of(wv.x - lo_f(hiA), wv.y - hi_f(hiA));
                uint32_t loB = bf16x2_of(wv.z - lo_f(hiB), wv.w - hi_f(hiB));
                uint32_t* dst = (uint32_t*)(Wpk + ((nt * 8 + ks) * 32 + gj * 4 + tidA));
                dst[hiword]         = hiA;
                dst[hiword + 2]     = loA;
                dst[4 + hiword]     = hiB;
                dst[4 + hiword + 2] = loB;
            }
        }
        __syncthreads();

        float acc[8][4];
        #pragma unroll
        for (int nt = 0; nt < 8; ++nt)
            #pragma unroll
            for (int q = 0; q < 4; ++q) acc[nt][q] = 0.0f;

        #pragma unroll
        for (int ks = 0; ks < 8; ++ks) {
            const int c0 = ks * 16 + 2 * tid;
            const float* xr0 = Xs + (mbase + g) * SSTR + c0;
            const float* xr1 = Xs + (mbase + g + 8) * SSTR + c0;
            float2 x00 = *(const float2*)(xr0);
            float2 x02 = *(const float2*)(xr0 + 8);
            float2 x10 = *(const float2*)(xr1);
            float2 x12 = *(const float2*)(xr1 + 8);
            uint32_t ah0 = bf16x2_of(x00.x, x00.y);
            uint32_t ah1 = bf16x2_of(x10.x, x10.y);
            uint32_t ah2 = bf16x2_of(x02.x, x02.y);
            uint32_t ah3 = bf16x2_of(x12.x, x12.y);
            uint32_t al0 = bf16x2_of(x00.x - lo_f(ah0), x00.y - hi_f(ah0));
            uint32_t al1 = bf16x2_of(x10.x - lo_f(ah1), x10.y - hi_f(ah1));
            uint32_t al2 = bf16x2_of(x02.x - lo_f(ah2), x02.y - hi_f(ah2));
            uint32_t al3 = bf16x2_of(x12.x - lo_f(ah3), x12.y - hi_f(ah3));

            #pragma unroll
            for (int nt = 0; nt < 8; ++nt) {
                const int ntg = nhalf * 8 + nt;
                uint4 w = Wpk[(ntg * 8 + ks) * 32 + lane];
                mma_bf16(acc[nt][0], acc[nt][1], acc[nt][2], acc[nt][3],
                         ah0, ah1, ah2, ah3, w.x, w.y);
                mma_bf16(acc[nt][0], acc[nt][1], acc[nt][2], acc[nt][3],
                         al0, al1, al2, al3, w.x, w.y);
                mma_bf16(acc[nt][0], acc[nt][1], acc[nt][2], acc[nt][3],
                         ah0, ah1, ah2, ah3, w.z, w.w);
            }
        }

        __syncthreads();

        float* T = (float*)Wpk;
        #pragma unroll
        for (int nt = 0; nt < 8; ++nt) {
            const int j0 = nhalf * 64 + nt * 8 + 2 * tid;
            const float b0v = __ldg(bias + j0);
            const float b1v = __ldg(bias + j0 + 1);
            float v0 = acc[nt][0] + b0v;
            float v1 = acc[nt][1] + b1v;
            float v2 = acc[nt][2] + b0v;
            float v3 = acc[nt][3] + b1v;
            v0 = 1.0f / (1.0f + __expf(-v0));
            v1 = 1.0f / (1.0f + __expf(-v1));
            v2 = 1.0f / (1.0f + __expf(-v2));
            v3 = 1.0f / (1.0f + __expf(-v3));
            T[j0 * SSTR + mbase + g]           = v0;
            T[(j0 + 1) * SSTR + mbase + g]     = v1;
            T[j0 * SSTR + mbase + g + 8]       = v2;
            T[(j0 + 1) * SSTR + mbase + g + 8] = v3;
        }
        __syncthreads();

        #pragma unroll
        for (int it = 0; it < 8; ++it) {
            const int idx = t + it * 512;
            const int j   = idx >> 5;
            const int m4  = (idx & 31) << 2;
            float4 v = *(const float4*)(T + j * SSTR + m4);
            *(float4*)(OutT + ((size_t)bidx * CDIM + j) * NSEQ + n0 + m4) = v;
        }
    }
}

// ---------------------------------------------------------------------------
// Kernel 2: per-(b,c) dual-softmax attention, float4-vectorized, no transposes.
// Row-major smem with stride 36 (LDS.128 per-lane rows conflict-free).
// ---------------------------------------------------------------------------
__global__ __launch_bounds__(256) void attn_kernel()
{
    extern __shared__ float asm_[];
    float* Qs  = asm_;               // [64][KSTR]  2304
    float* Ks  = Qs + HP * KSTR;     // [64][KSTR]
    float* Vs  = Ks + HP * KSTR;     // [64][KSTR]
    float* qp  = Vs + HP * KSTR;     // [32][KSTR]  1152
    float* kp  = qp + HG * KSTR;     // [32][KSTR]
    float* Kqv = kp + HG * KSTR;     // [32][KSTR]
    float* buf = Kqv + HG * KSTR;    // [8][288]

    const int bc = blockIdx.x;
    const float* Qg = g_QT + (size_t)bc * NSEQ;
    const float* Kg = g_KT + (size_t)bc * NSEQ;
    const float* Vg = g_VT + (size_t)bc * NSEQ;
    float* Op = g_VT + (size_t)bc * NSEQ;        // overwrite V plane

    const int t    = threadIdx.x;
    const int warp = t >> 5;
    const int lane = t & 31;
    float* wbuf = buf + warp * 288;

    // ---- Load Q, K, V row-major (padded stride) ----
    #pragma unroll
    for (int i = 0; i < 2; ++i) {
        const int idx = (t + i * 256) * 4;       // 0..8188
        const int s   = (idx >> 5) * KSTR + (idx & 31);
        *(float4*)(Qs + s) = *(const float4*)(Qg + idx);
        *(float4*)(Ks + s) = *(const float4*)(Kg + idx);
        *(float4*)(Vs + s) = *(const float4*)(Vg + idx);
    }
    __syncthreads();

    // ---- Pool over h pairs ----
    {
        const int g  = t >> 3;
        const int w4 = (t & 7) << 2;
        float4 a = *(const float4*)(Qs + (2 * g) * KSTR + w4);
        float4 b = *(const float4*)(Qs + (2 * g + 1) * KSTR + w4);
        *(float4*)(qp + g * KSTR + w4) =
            make_float4(0.5f * (a.x + b.x), 0.5f * (a.y + b.y),
                        0.5f * (a.z + b.z), 0.5f * (a.w + b.w));
        float4 c = *(const float4*)(Ks + (2 * g) * KSTR + w4);
        float4 d = *(const float4*)(Ks + (2 * g + 1) * KSTR + w4);
        *(float4*)(kp + g * KSTR + w4) =
            make_float4(0.5f * (c.x + d.x), 0.5f * (c.y + d.y),
                        0.5f * (c.z + d.z), 0.5f * (c.w + d.w));
    }
    __syncthreads();

    // ---- Phase A: S1[g][h] = qp[g]·K[h];  warp owns g0..g0+3; h = lane, lane+32 ----
    {
        const int g0 = warp * 4;
        float4 a0[4], a1[4];
        #pragma unroll
        for (int gi = 0; gi < 4; ++gi) { a0[gi] = make_float4(0,0,0,0); a1[gi] = make_float4(0,0,0,0); }
        #pragma unroll
        for (int w0 = 0; w0 < 32; w0 += 4) {
            float4 k0 = *(const float4*)(Ks + lane * KSTR + w0);
            float4 k1 = *(const float4*)(Ks + (lane + 32) * KSTR + w0);
            #pragma unroll
            for (int gi = 0; gi < 4; ++gi) {
                float4 qv = *(const float4*)(qp + (g0 + gi) * KSTR + w0);
                a0[gi].x = fmaf(qv.x, k0.x, a0[gi].x);
                a0[gi].y = fmaf(qv.y, k0.y, a0[gi].y);
                a0[gi].z = fmaf(qv.z, k0.z, a0[gi].z);
                a0[gi].w = fmaf(qv.w, k0.w, a0[gi].w);
                a1[gi].x = fmaf(qv.x, k1.x, a1[gi].x);
                a1[gi].y = fmaf(qv.y, k1.y, a1[gi].y);
                a1[gi].z = fmaf(qv.z, k1.z, a1[gi].z);
                a1[gi].w = fmaf(qv.w, k1.w, a1[gi].w);
            }
        }
        #pragma unroll
        for (int gi = 0; gi < 4; ++gi) {
            float a = ((a0[gi].x + a0[gi].y) + (a0[gi].z + a0[gi].w)) * D_SCALE;
            float b = ((a1[gi].x + a1[gi].y) + (a1[gi].z + a1[gi].w)) * D_SCALE;
            float m = fmaxf(a, b);
            #pragma unroll
            for (int o = 16; o; o >>= 1) m = fmaxf(m, __shfl_xor_sync(0xffffffffu, m, o));
            float e0 = __expf(a - m), e1 = __expf(b - m);
            float sum = e0 + e1;
            #pragma unroll
            for (int o = 16; o; o >>= 1) sum += __shfl_xor_sync(0xffffffffu, sum, o);
            float r = __frcp_rn(sum);
            wbuf[gi * 68 + lane]      = e0 * r;
            wbuf[gi * 68 + 32 + lane] = e1 * r;
        }
        __syncwarp();

        // ---- Phase B: Kqv[g][w] = sum_h P[g][h] V[h][w] ----
        const int gi = lane >> 3;
        const int w4 = (lane & 7) << 2;
        float4 acc = make_float4(0, 0, 0, 0);
        #pragma unroll
        for (int h0 = 0; h0 < 64; h0 += 4) {
            float4 pv = *(const float4*)(wbuf + gi * 68 + h0);
            float4 v0 = *(const float4*)(Vs + (h0 + 0) * KSTR + w4);
            float4 v1 = *(const float4*)(Vs + (h0 + 1) * KSTR + w4);
            float4 v2 = *(const float4*)(Vs + (h0 + 2) * KSTR + w4);
            float4 v3 = *(const float4*)(Vs + (h0 + 3) * KSTR + w4);
            acc.x = fmaf(pv.x, v0.x, acc.x); acc.y = fmaf(pv.x, v0.y, acc.y);
            acc.z = fmaf(pv.x, v0.z, acc.z); acc.w = fmaf(pv.x, v0.w, acc.w);
            acc.x = fmaf(pv.y, v1.x, acc.x); acc.y = fmaf(pv.y, v1.y, acc.y);
            acc.z = fmaf(pv.y, v1.z, acc.z); acc.w = fmaf(pv.y, v1.w, acc.w);
            acc.x = fmaf(pv.z, v2.x, acc.x); acc.y = fmaf(pv.z, v2.y, acc.y);
            acc.z = fmaf(pv.z, v2.z, acc.z); acc.w = fmaf(pv.z, v2.w, acc.w);
            acc.x = fmaf(pv.w, v3.x, acc.x); acc.y = fmaf(pv.w, v3.y, acc.y);
            acc.z = fmaf(pv.w, v3.z, acc.z); acc.w = fmaf(pv.w, v3.w, acc.w);
        }
        *(float4*)(Kqv + (g0 + gi) * KSTR + w4) = acc;
    }
    __syncthreads();

    // ---- Phase C: S2[h][g] = Q[h]·kp[g]; warp owns h0..h0+7; lane = g ----
    {
        const int h0 = warp * 8;
        float4 acc[8];
        #pragma unroll
        for (int hi = 0; hi < 8; ++hi) acc[hi] = make_float4(0, 0, 0, 0);
        #pragma unroll
        for (int w0 = 0; w0 < 32; w0 += 4) {
            float4 kr = *(const float4*)(kp + lane * KSTR + w0);
            #pragma unroll
            for (int hi = 0; hi < 8; ++hi) {
                float4 qr = *(const float4*)(Qs + (h0 + hi) * KSTR + w0);
                acc[hi].x = fmaf(qr.x, kr.x, acc[hi].x);
                acc[hi].y = fmaf(qr.y, kr.y, acc[hi].y);
                acc[hi].z = fmaf(qr.z, kr.z, acc[hi].z);
                acc[hi].w = fmaf(qr.w, kr.w, acc[hi].w);
            }
        }
        #pragma unroll
        for (int hi = 0; hi < 8; ++hi) {
            float a = ((acc[hi].x + acc[hi].y) + (acc[hi].z + acc[hi].w)) * D_SCALE;
            float m = a;
            #pragma unroll
            for (int o = 16; o; o >>= 1) m = fmaxf(m, __shfl_xor_sync(0xffffffffu, m, o));
            float e = __expf(a - m);
            float sum = e;
            #pragma unroll
            for (int o = 16; o; o >>= 1) sum += __shfl_xor_sync(0xffffffffu, sum, o);
            wbuf[hi * 36 + lane] = e * __frcp_rn(sum);
        }
        __syncwarp();

        // ---- Phase D: out[h][w] = sum_g P2[h][g] Kqv[g][w] ----
        const int w4 = (lane & 7) << 2;
        #pragma unroll
        for (int hh = 0; hh < 2; ++hh) {
            const int hi = hh * 4 + (lane >> 3);
            float4 acc2 = make_float4(0, 0, 0, 0);
            #pragma unroll
            for (int g0 = 0; g0 < 32; g0 += 4) {
                float4 pv = *(const float4*)(wbuf + hi * 36 + g0);
                float4 v0 = *(const float4*)(Kqv + (g0 + 0) * KSTR + w4);
                float4 v1 = *(const float4*)(Kqv + (g0 + 1) * KSTR + w4);
                float4 v2 = *(const float4*)(Kqv + (g0 + 2) * KSTR + w4);
                float4 v3 = *(const float4*)(Kqv + (g0 + 3) * KSTR + w4);
                acc2.x = fmaf(pv.x, v0.x, acc2.x); acc2.y = fmaf(pv.x, v0.y, acc2.y);
                acc2.z = fmaf(pv.x, v0.z, acc2.z); acc2.w = fmaf(pv.x, v0.w, acc2.w);
                acc2.x = fmaf(pv.y, v1.x, acc2.x); acc2.y = fmaf(pv.y, v1.y, acc2.y);
                acc2.z = fmaf(pv.y, v1.z, acc2.z); acc2.w = fmaf(pv.y, v1.w, acc2.w);
                acc2.x = fmaf(pv.z, v2.x, acc2.x); acc2.y = fmaf(pv.z, v2.y, acc2.y);
                acc2.z = fmaf(pv.z, v2.z, acc2.z); acc2.w = fmaf(pv.z, v2.w, acc2.w);
                acc2.x = fmaf(pv.w, v3.x, acc2.x); acc2.y = fmaf(pv.w, v3.y, acc2.y);
                acc2.z = fmaf(pv.w, v3.z, acc2.z); acc2.w = fmaf(pv.w, v3.w, acc2.w);
            }
            *(float4*)(Op + (h0 + hi) * 32 + w4) = acc2;
        }
    }
}

// ---------------------------------------------------------------------------
// Kernel 3: [B, C, N] -> [B, N, C] transpose (output epilogue).
// ---------------------------------------------------------------------------
__global__ __launch_bounds__(256) void transpose_kernel(float* __restrict__ out)
{
    __shared__ float tile[32][33];
    const int b  = blockIdx.z;
    const int c0 = blockIdx.y * 32;
    const int n0 = blockIdx.x * 32;
    const int tx = threadIdx.x;
    const int ty = threadIdx.y;

    const float* src = g_VT + (size_t)b * CDIM * NSEQ;
    #pragma unroll
    for (int i = 0; i < 32; i += 8)
        tile[ty + i][tx] = src[(size_t)(c0 + ty + i) * NSEQ + n0 + tx];
    __syncthreads();
    #pragma unroll
    for (int i = 0; i < 32; i += 8)
        out[((size_t)b * NSEQ + n0 + ty + i) * CDIM + c0 + tx] = tile[tx][ty + i];
}

// ---------------------------------------------------------------------------
extern "C" void kernel_launch(void* const* d_in, const int* in_sizes, int n_in,
                              void* d_out, int out_size)
{
    (void)in_sizes; (void)n_in; (void)out_size;
    const float* X  = (const float*)d_in[0];
    const float* Wq = (const float*)d_in[1];
    const float* bq = (const float*)d_in[2];
    const float* Wk = (const float*)d_in[3];
    const float* bk = (const float*)d_in[4];
    const float* Wv = (const float*)d_in[5];
    const float* bv = (const float*)d_in[6];
    float* out = (float*)d_out;

    const size_t proj_smem = (size_t)2 * 128 * SSTR * sizeof(float);  // 135168 B
    cudaFuncSetAttribute(proj_mma_kernel, cudaFuncAttributeMaxDynamicSharedMemorySize,
                         (int)proj_smem);

    // Qs,Ks,Vs (3*64*36) + qp,kp,Kqv (3*32*36) + buf (8*288) = 12672 floats
    const size_t attn_smem = (size_t)12672 * sizeof(float);           // 50688 B
    cudaFuncSetAttribute(attn_kernel, cudaFuncAttributeMaxDynamicSharedMemorySize,
                         (int)attn_smem);

    proj_mma_kernel<<<dim3(1024, 1, 1), 512, proj_smem>>>(X, Wq, bq, Wk, bk, Wv, bv);
    attn_kernel<<<dim3(BATCH * CDIM, 1, 1), 256, attn_smem>>>();
    transpose_kernel<<<dim3(NSEQ / 32, CDIM / 32, BATCH), dim3(32, 8, 1)>>>(out);
}

// round 7
// speedup vs baseline: 1.3434x; 1.3434x over previous
#include <cuda_runtime.h>
#include <cstdint>

#define BATCH 64
#define NSEQ  2048
#define CDIM  128
#define HP    64
#define WP    32
#define HG    32   // HP / POOL
#define D_SCALE 0.08838834764831845f  // 1/sqrt(128)

// Scratch: Q,K,V in [B, C, N] (spatial-major) layout. V plane is overwritten
// with the attention output by attn_kernel (each CTA exclusively owns its plane,
// and proj writes it fully on every graph replay -> deterministic).
__device__ float g_QT[(size_t)BATCH * CDIM * NSEQ];
__device__ float g_KT[(size_t)BATCH * CDIM * NSEQ];
__device__ float g_VT[(size_t)BATCH * CDIM * NSEQ];

// Precomputed W fragments: [p][(nt*8+ks)*32 + lane] -> uint4 (b0hi, b1hi, b0lo, b1lo)
__device__ uint4 g_Wpk[3 * 4096];

#define SSTR 132   // proj smem row stride (floats)

// Pack two fp32 into bf16x2: e0 -> low 16 bits (even k), e1 -> high (odd k).
__device__ __forceinline__ uint32_t bf16x2_of(float e0, float e1) {
    uint32_t r;
    asm("cvt.rn.bf16x2.f32 %0, %1, %2;" : "=r"(r) : "f"(e1), "f"(e0));
    return r;
}
__device__ __forceinline__ float lo_f(uint32_t p) { return __uint_as_float(p << 16); }
__device__ __forceinline__ float hi_f(uint32_t p) { return __uint_as_float(p & 0xffff0000u); }

__device__ __forceinline__ void mma_bf16(float& d0, float& d1, float& d2, float& d3,
                                         uint32_t a0, uint32_t a1, uint32_t a2, uint32_t a3,
                                         uint32_t b0, uint32_t b1) {
    asm volatile(
        "mma.sync.aligned.m16n8k16.row.col.f32.bf16.bf16.f32 "
        "{%0,%1,%2,%3}, {%4,%5,%6,%7}, {%8,%9}, {%0,%1,%2,%3};"
        : "+f"(d0), "+f"(d1), "+f"(d2), "+f"(d3)
        : "r"(a0), "r"(a1), "r"(a2), "r"(a3), "r"(b0), "r"(b1));
}

// ---------------------------------------------------------------------------
// Kernel 0: convert W matrices into MMA-fragment-packed bf16 hi/lo, once.
// Slot sq of lane gj*4+sq: x = hi(k=2sq,2sq+1), y = hi(k=2sq+8,2sq+9),
// z/w = residual lo of x/y. (Layout identical to R4's in-CTA staging.)
// ---------------------------------------------------------------------------
__global__ __launch_bounds__(256) void prep_w_kernel(
    const float* __restrict__ Wq, const float* __restrict__ Wk,
    const float* __restrict__ Wv)
{
    const int p = blockIdx.x;
    const float* W = (p == 0) ? Wq : (p == 1) ? Wk : Wv;
    const int t = threadIdx.x;
    #pragma unroll
    for (int i = 0; i < 16; ++i) {
        const int pos  = t + i * 256;        // 0..4095
        const int lane = pos & 31;
        const int ks   = (pos >> 5) & 7;
        const int nt   = pos >> 8;
        const int gj   = lane >> 2;
        const int s    = lane & 3;
        const int j    = nt * 8 + gj;
        const int c0   = ks * 16 + 2 * s;
        const float w0 = W[j * CDIM + c0],     w1 = W[j * CDIM + c0 + 1];
        const float w2 = W[j * CDIM + c0 + 8], w3 = W[j * CDIM + c0 + 9];
        uint32_t x = bf16x2_of(w0, w1);
        uint32_t y = bf16x2_of(w2, w3);
        uint32_t z = bf16x2_of(w0 - lo_f(x), w1 - hi_f(x));
        uint32_t w = bf16x2_of(w2 - lo_f(y), w3 - hi_f(y));
        g_Wpk[p * 4096 + pos] = make_uint4(x, y, z, w);
    }
}

// ---------------------------------------------------------------------------
// Kernel 1: projection GEMMs (R4 structure; W staging replaced by a plain
// fragment copy from g_Wpk). 3-term bf16 split (hi*hi + lo*hi + hi*lo).
// 512 threads = 16 warps: warp = (mgroup 0..7) x (nhalf 0..1).
// Out[m,j] = sigmoid(sum_c X[m,c] W[j,c] + b[j]), stored transposed OutT[b][j][n].
// ---------------------------------------------------------------------------
__global__ __launch_bounds__(512) void proj_mma_kernel(
    const float* __restrict__ X,
    const float* __restrict__ bq, const float* __restrict__ bk,
    const float* __restrict__ bv)
{
    extern __shared__ float sm[];
    float* Xs  = sm;                        // [m][c] 128 x SSTR fp32 (67.6 KB)
    uint4* Wpk = (uint4*)(sm + 128 * SSTR); // [16 nt][8 ks][32 lane] uint4 (64 KB)

    const int t    = threadIdx.x;
    const int warp = t >> 5;
    const int lane = t & 31;
    const int M0   = blockIdx.x * 128;
    const int bidx = M0 >> 11;
    const int n0   = M0 & 2047;

    {
        const int r  = t >> 5;
        const int c4 = (t & 31) << 2;
        #pragma unroll
        for (int it = 0; it < 8; ++it) {
            const int row = it * 16 + r;
            float4 xv = *(const float4*)(X + (size_t)(M0 + row) * CDIM + c4);
            *(float4*)(Xs + row * SSTR + c4) = xv;
        }
    }

    const int g      = lane >> 2;
    const int tid    = lane & 3;
    const int mgroup = warp & 7;
    const int nhalf  = warp >> 3;
    const int mbase  = mgroup * 16;

    #pragma unroll 1
    for (int p = 0; p < 3; ++p) {
        const float* bias = (p == 0) ? bq : (p == 1) ? bk : bv;
        float* OutT       = (p == 0) ? g_QT : (p == 1) ? g_KT : g_VT;

        __syncthreads();   // prev epilogue done with Wpk region; Xs stable

        // ---- Stage W fragments: straight copy from precomputed global ----
        #pragma unroll
        for (int i = 0; i < 8; ++i)
            Wpk[t + i * 512] = g_Wpk[p * 4096 + t + i * 512];
        __syncthreads();

        // ---- MMA mainloop: warp owns 16 m-rows x 64 j-cols (8 nt) ----
        float acc[8][4];
        #pragma unroll
        for (int nt = 0; nt < 8; ++nt)
            #pragma unroll
            for (int q = 0; q < 4; ++q) acc[nt][q] = 0.0f;

        #pragma unroll
        for (int ks = 0; ks < 8; ++ks) {
            const int c0 = ks * 16 + 2 * tid;
            const float* xr0 = Xs + (mbase + g) * SSTR + c0;
            const float* xr1 = Xs + (mbase + g + 8) * SSTR + c0;
            float2 x00 = *(const float2*)(xr0);
            float2 x02 = *(const float2*)(xr0 + 8);
            float2 x10 = *(const float2*)(xr1);
            float2 x12 = *(const float2*)(xr1 + 8);
            uint32_t ah0 = bf16x2_of(x00.x, x00.y);
            uint32_t ah1 = bf16x2_of(x10.x, x10.y);
            uint32_t ah2 = bf16x2_of(x02.x, x02.y);
            uint32_t ah3 = bf16x2_of(x12.x, x12.y);
            uint32_t al0 = bf16x2_of(x00.x - lo_f(ah0), x00.y - hi_f(ah0));
            uint32_t al1 = bf16x2_of(x10.x - lo_f(ah1), x10.y - hi_f(ah1));
            uint32_t al2 = bf16x2_of(x02.x - lo_f(ah2), x02.y - hi_f(ah2));
            uint32_t al3 = bf16x2_of(x12.x - lo_f(ah3), x12.y - hi_f(ah3));

            #pragma unroll
            for (int nt = 0; nt < 8; ++nt) {
                const int ntg = nhalf * 8 + nt;
                uint4 w = Wpk[(ntg * 8 + ks) * 32 + lane];
                mma_bf16(acc[nt][0], acc[nt][1], acc[nt][2], acc[nt][3],
                         ah0, ah1, ah2, ah3, w.x, w.y);
                mma_bf16(acc[nt][0], acc[nt][1], acc[nt][2], acc[nt][3],
                         al0, al1, al2, al3, w.x, w.y);
                mma_bf16(acc[nt][0], acc[nt][1], acc[nt][2], acc[nt][3],
                         ah0, ah1, ah2, ah3, w.z, w.w);
            }
        }

        __syncthreads();   // all warps done reading Wpk -> reuse as transpose buf

        // ---- Epilogue: bias + sigmoid, transpose to [j][m] via smem ----
        float* T = (float*)Wpk;
        #pragma unroll
        for (int nt = 0; nt < 8; ++nt) {
            const int j0 = nhalf * 64 + nt * 8 + 2 * tid;
            const float b0v = __ldg(bias + j0);
            const float b1v = __ldg(bias + j0 + 1);
            float v0 = acc[nt][0] + b0v;
            float v1 = acc[nt][1] + b1v;
            float v2 = acc[nt][2] + b0v;
            float v3 = acc[nt][3] + b1v;
            v0 = 1.0f / (1.0f + __expf(-v0));
            v1 = 1.0f / (1.0f + __expf(-v1));
            v2 = 1.0f / (1.0f + __expf(-v2));
            v3 = 1.0f / (1.0f + __expf(-v3));
            T[j0 * SSTR + mbase + g]           = v0;
            T[(j0 + 1) * SSTR + mbase + g]     = v1;
            T[j0 * SSTR + mbase + g + 8]       = v2;
            T[(j0 + 1) * SSTR + mbase + g + 8] = v3;
        }
        __syncthreads();

        // ---- Coalesced float4 store: OutT[bidx][j][n0 + m] ----
        #pragma unroll
        for (int it = 0; it < 8; ++it) {
            const int idx = t + it * 512;
            const int j   = idx >> 5;
            const int m4  = (idx & 31) << 2;
            float4 v = *(const float4*)(T + j * SSTR + m4);
            *(float4*)(OutT + ((size_t)bidx * CDIM + j) * NSEQ + n0 + m4) = v;
        }
    }
}

// ---------------------------------------------------------------------------
// Kernel 2: per-(b,c) dual-softmax attention on a [64,32] plane (R4 version).
// ---------------------------------------------------------------------------
__global__ __launch_bounds__(256) void attn_kernel()
{
    const int bc = blockIdx.x;                      // b*128 + c
    const float* Qp = g_QT + (size_t)bc * NSEQ;
    const float* Kp = g_KT + (size_t)bc * NSEQ;
    const float* Vp = g_VT + (size_t)bc * NSEQ;
    float* Op = g_VT + (size_t)bc * NSEQ;           // overwrite V plane

    __shared__ float Qs[HP * WP];     // [h][w]
    __shared__ float Vs[HP * WP];     // [h][w]
    __shared__ float KTs[WP * 65];    // [w][h], padded
    __shared__ float kTs[WP * 33];    // [w][g], pooled K, padded
    __shared__ float qs[HG * WP];     // [g][w], pooled Q
    __shared__ float Kqvs[HG * WP];   // [g][w]
    __shared__ float buf[8][264];     // per-warp softmax rows

    const int t    = threadIdx.x;
    const int warp = t >> 5;
    const int lane = t & 31;

    #pragma unroll
    for (int i = 0; i < 2; ++i) {
        int idx = (t + i * 256) * 4;
        float4 qv = *(const float4*)(Qp + idx);
        float4 vv = *(const float4*)(Vp + idx);
        float4 kv = *(const float4*)(Kp + idx);
        *(float4*)(Qs + idx) = qv;
        *(float4*)(Vs + idx) = vv;
        int h = idx >> 5, w = idx & 31;
        KTs[(w + 0) * 65 + h] = kv.x;
        KTs[(w + 1) * 65 + h] = kv.y;
        KTs[(w + 2) * 65 + h] = kv.z;
        KTs[(w + 3) * 65 + h] = kv.w;
    }
    __syncthreads();

    #pragma unroll
    for (int i = 0; i < 4; ++i) {
        int idx = t + i * 256;
        int g = idx >> 5, w = idx & 31;
        qs[g * 32 + w]  = 0.5f * (Qs[(2 * g) * 32 + w] + Qs[(2 * g + 1) * 32 + w]);
        kTs[w * 33 + g] = 0.5f * (KTs[w * 65 + 2 * g] + KTs[w * 65 + 2 * g + 1]);
    }
    __syncthreads();

    // ---- Kq = softmax_h(scale * q @ K^T), Kqv = Kq @ V ----
    {
        const int g0 = warp * 4;
        float s0[4] = {0, 0, 0, 0}, s1[4] = {0, 0, 0, 0};
        #pragma unroll
        for (int w = 0; w < 32; ++w) {
            float k0 = KTs[w * 65 + lane];
            float k1 = KTs[w * 65 + 32 + lane];
            #pragma unroll
            for (int gi = 0; gi < 4; ++gi) {
                float qv = qs[(g0 + gi) * 32 + w];
                s0[gi] = fmaf(qv, k0, s0[gi]);
                s1[gi] = fmaf(qv, k1, s1[gi]);
            }
        }
        #pragma unroll
        for (int gi = 0; gi < 4; ++gi) {
            float a = s0[gi] * D_SCALE, b = s1[gi] * D_SCALE;
            float m = fmaxf(a, b);
            #pragma unroll
            for (int o = 16; o; o >>= 1) m = fmaxf(m, __shfl_xor_sync(0xffffffffu, m, o));
            float e0 = __expf(a - m), e1 = __expf(b - m);
            float sum = e0 + e1;
            #pragma unroll
            for (int o = 16; o; o >>= 1) sum += __shfl_xor_sync(0xffffffffu, sum, o);
            float r = __frcp_rn(sum);
            buf[warp][gi * 66 + lane]      = e0 * r;
            buf[warp][gi * 66 + 32 + lane] = e1 * r;
        }
        __syncwarp();
        const int gi = lane >> 3;
        const int w4 = (lane & 7) << 2;
        float4 acc = {0, 0, 0, 0};
        #pragma unroll 8
        for (int h = 0; h < 64; ++h) {
            float p  = buf[warp][gi * 66 + h];
            float4 v = *(const float4*)(Vs + h * 32 + w4);
            acc.x = fmaf(p, v.x, acc.x);
            acc.y = fmaf(p, v.y, acc.y);
            acc.z = fmaf(p, v.z, acc.z);
            acc.w = fmaf(p, v.w, acc.w);
        }
        *(float4*)(Kqvs + (g0 + gi) * 32 + w4) = acc;
    }
    __syncthreads();

    // ---- Qk = softmax_g(scale * Q @ k^T), out = Qk @ Kqv ----
    {
        const int h0 = warp * 8;
        float s[8] = {0, 0, 0, 0, 0, 0, 0, 0};
        #pragma unroll
        for (int w = 0; w < 32; ++w) {
            float kt = kTs[w * 33 + lane];
            #pragma unroll
            for (int hi = 0; hi < 8; ++hi)
                s[hi] = fmaf(Qs[(h0 + hi) * 32 + w], kt, s[hi]);
        }
        #pragma unroll
        for (int hi = 0; hi < 8; ++hi) {
            float a = s[hi] * D_SCALE;
            float m = a;
            #pragma unroll
            for (int o = 16; o; o >>= 1) m = fmaxf(m, __shfl_xor_sync(0xffffffffu, m, o));
            float e = __expf(a - m);
            float sum = e;
            #pragma unroll
            for (int o = 16; o; o >>= 1) sum += __shfl_xor_sync(0xffffffffu, sum, o);
            buf[warp][hi * 33 + lane] = e * __frcp_rn(sum);
        }
        __syncwarp();
        const int hi = lane >> 2;
        const int w8 = (lane & 3) << 3;
        float4 acc0 = {0, 0, 0, 0}, acc1 = {0, 0, 0, 0};
        #pragma unroll 8
        for (int g = 0; g < 32; ++g) {
            float p   = buf[warp][hi * 33 + g];
            float4 v0 = *(const float4*)(Kqvs + g * 32 + w8);
            float4 v1 = *(const float4*)(Kqvs + g * 32 + w8 + 4);
            acc0.x = fmaf(p, v0.x, acc0.x);
            acc0.y = fmaf(p, v0.y, acc0.y);
            acc0.z = fmaf(p, v0.z, acc0.z);
            acc0.w = fmaf(p, v0.w, acc0.w);
            acc1.x = fmaf(p, v1.x, acc1.x);
            acc1.y = fmaf(p, v1.y, acc1.y);
            acc1.z = fmaf(p, v1.z, acc1.z);
            acc1.w = fmaf(p, v1.w, acc1.w);
        }
        float* dst = Op + (h0 + hi) * 32 + w8;
        *(float4*)(dst)     = acc0;
        *(float4*)(dst + 4) = acc1;
    }
}

// ---------------------------------------------------------------------------
// Kernel 3: [B, C, N] -> [B, N, C] transpose (output epilogue).
// ---------------------------------------------------------------------------
__global__ __launch_bounds__(256) void transpose_kernel(float* __restrict__ out)
{
    __shared__ float tile[32][33];
    const int b  = blockIdx.z;
    const int c0 = blockIdx.y * 32;
    const int n0 = blockIdx.x * 32;
    const int tx = threadIdx.x;
    const int ty = threadIdx.y;

    const float* src = g_VT + (size_t)b * CDIM * NSEQ;
    #pragma unroll
    for (int i = 0; i < 32; i += 8)
        tile[ty + i][tx] = src[(size_t)(c0 + ty + i) * NSEQ + n0 + tx];
    __syncthreads();
    #pragma unroll
    for (int i = 0; i < 32; i += 8)
        out[((size_t)b * NSEQ + n0 + ty + i) * CDIM + c0 + tx] = tile[tx][ty + i];
}

// ---------------------------------------------------------------------------
extern "C" void kernel_launch(void* const* d_in, const int* in_sizes, int n_in,
                              void* d_out, int out_size)
{
    (void)in_sizes; (void)n_in; (void)out_size;
    const float* X  = (const float*)d_in[0];
    const float* Wq = (const float*)d_in[1];
    const float* bq = (const float*)d_in[2];
    const float* Wk = (const float*)d_in[3];
    const float* bk = (const float*)d_in[4];
    const float* Wv = (const float*)d_in[5];
    const float* bv = (const float*)d_in[6];
    float* out = (float*)d_out;

    const size_t proj_smem = (size_t)2 * 128 * SSTR * sizeof(float);  // 135168 B
    cudaFuncSetAttribute(proj_mma_kernel, cudaFuncAttributeMaxDynamicSharedMemorySize,
                         (int)proj_smem);

    prep_w_kernel<<<dim3(3, 1, 1), 256>>>(Wq, Wk, Wv);
    proj_mma_kernel<<<dim3(1024, 1, 1), 512, proj_smem>>>(X, bq, bk, bv);
    attn_kernel<<<dim3(BATCH * CDIM, 1, 1), 256>>>();
    transpose_kernel<<<dim3(NSEQ / 32, CDIM / 32, BATCH), dim3(32, 8, 1)>>>(out);
}